// round 8
// baseline (speedup 1.0000x reference)
#include <cuda_runtime.h>
#include <cuda_bf16.h>
#include <cstdint>

#define BS    16384
#define NCH   8
#define HDIM  256
#define RANK  16
#define NAGG  4
#define TDIM  64
#define RCOLS 272
#define NEED  256
#define NCA   (NCH*NAGG)        // 32
#define NBT   (BS/16)           // 1024 real 16-row tiles
#define NTILE 7                 // tiles per CTA (uniform)
#define NCTA  148
#define NBT_PAD (NCTA*NTILE)    // 1036 virtual tiles
#define MROWS (NTILE*16)        // 112 rows per CTA

// ---------------- fragment-major operand scratch ---------------------------
// A frags: [c][tile(1036)][kt(16)][lane(32)] x uint4 ; hi and lo
__device__ uint4 g_Afr_h[(size_t)NCH * NBT_PAD * 16 * 32];
__device__ uint4 g_Afr_l[(size_t)NCH * NBT_PAD * 16 * 32];
// B frags packed: [ca][nt(32)][kt(16)][lane(32)] x uint4 {bh0,bh1,bl0,bl1}
__device__ uint4 g_Bfr[(size_t)NCA * 32 * 16 * 32];

// ---------------- helpers ---------------------------------------------------
__device__ __forceinline__ uint32_t pack_hi2(float x, float y) {
    __nv_bfloat162 p = {__float2bfloat16(x), __float2bfloat16(y)};
    return *(uint32_t*)&p;
}
__device__ __forceinline__ uint32_t pack_lo2(float x, float y) {
    float hx = __bfloat162float(__float2bfloat16(x));
    float hy = __bfloat162float(__float2bfloat16(y));
    __nv_bfloat162 p = {__float2bfloat16(x - hx), __float2bfloat16(y - hy)};
    return *(uint32_t*)&p;
}
// NOTE: non-volatile asm — results flow through "+f" operands, so the compiler
// may interleave/schedule these freely (crucial for hiding HMMA latency).
__device__ __forceinline__ void mma16816(float* d, uint32_t a0, uint32_t a1,
                                         uint32_t a2, uint32_t a3,
                                         uint32_t b0, uint32_t b1) {
    asm("mma.sync.aligned.m16n8k16.row.col.f32.bf16.bf16.f32 "
        "{%0,%1,%2,%3}, {%4,%5,%6,%7}, {%8,%9}, {%0,%1,%2,%3};"
        : "+f"(d[0]), "+f"(d[1]), "+f"(d[2]), "+f"(d[3])
        : "r"(a0), "r"(a1), "r"(a2), "r"(a3), "r"(b0), "r"(b1));
}

// ---------------- prep A: nb fp32 -> hi/lo bf16 mma fragments ---------------
__global__ __launch_bounds__(256) void tt_prep_a(const float* __restrict__ nb) {
    size_t t = (size_t)blockIdx.x * 256 + threadIdx.x;   // [c][bt(1024)][kt][lane]
    int lane = (int)(t & 31);
    int kt   = (int)((t >> 5) & 15);
    int bt   = (int)((t >> 9) & (NBT - 1));
    int c    = (int)(t >> 19);
    int g = lane >> 2, tg = lane & 3;
    int r0 = bt * 16 + g, r1 = r0 + 8;
    int k0 = kt * 16 + tg * 2;
    const float* p0 = nb + ((size_t)r0 * NCH + c) * HDIM;
    const float* p1 = nb + ((size_t)r1 * NCH + c) * HDIM;
    float2 v0 = *(const float2*)(p0 + k0);
    float2 v1 = *(const float2*)(p1 + k0);
    float2 v2 = *(const float2*)(p0 + k0 + 8);
    float2 v3 = *(const float2*)(p1 + k0 + 8);
    size_t o = (((size_t)c * NBT_PAD + bt) * 16 + kt) * 32 + lane;
    g_Afr_h[o] = make_uint4(pack_hi2(v0.x, v0.y), pack_hi2(v1.x, v1.y),
                            pack_hi2(v2.x, v2.y), pack_hi2(v3.x, v3.y));
    g_Afr_l[o] = make_uint4(pack_lo2(v0.x, v0.y), pack_lo2(v1.x, v1.y),
                            pack_lo2(v2.x, v2.y), pack_lo2(v3.x, v3.y));
}

// ---------------- prep B: U fp32 -> packed hi/lo bf16 fragments -------------
__global__ __launch_bounds__(256) void tt_prep_b(const float* __restrict__ U) {
    size_t t = (size_t)blockIdx.x * 256 + threadIdx.x;   // [ca][nt(32)][kt][lane]
    int lane = (int)(t & 31);
    int kt   = (int)((t >> 5) & 15);
    int nt   = (int)((t >> 9) & 31);
    int ca   = (int)(t >> 14);
    int g = lane >> 2, tg = lane & 3;
    int n  = nt * 8 + g;
    int k0 = kt * 16 + tg * 2;
    const float* base = U + (size_t)ca * HDIM * RCOLS + n;
    float x0 = base[(size_t)(k0)     * RCOLS];
    float x1 = base[(size_t)(k0 + 1) * RCOLS];
    float x2 = base[(size_t)(k0 + 8) * RCOLS];
    float x3 = base[(size_t)(k0 + 9) * RCOLS];
    g_Bfr[t] = make_uint4(pack_hi2(x0, x1), pack_hi2(x2, x3),
                          pack_lo2(x0, x1), pack_lo2(x2, x3));
}

// ---------------- fused kernel ----------------------------------------------
#define PPAD      264
#define OFF_BIAS  (MROWS * 64 * 4)            // carry: 112*64*4 = 28672
#define OFF_P     (OFF_BIAS + 1024)           // 29696
#define SMEM_TOT  (OFF_P + MROWS * PPAD * 4)  // 147968

__global__ __launch_bounds__(256, 1) void tt_fused(
    const float* __restrict__ te,   // [BS][TDIM]
    const float* __restrict__ bb,   // [NCH][NAGG][1][RCOLS]
    const float* __restrict__ Ut,   // [NAGG][TDIM][RANK]
    const float* __restrict__ bt,   // [NAGG][1][RANK]
    const float* __restrict__ Uo,   // [NAGG][RANK][HDIM]
    const float* __restrict__ bo,   // [NAGG][1][HDIM]
    float* __restrict__ out)        // [BS][NAGG*HDIM]
{
    extern __shared__ char smem[];
    float* s_carry = (float*)smem;                   // [112][4][16]
    float* s_bias  = (float*)(smem + OFF_BIAS);      // [256]
    float* s_P     = (float*)(smem + OFF_P);         // [112][264]

    const int tid  = threadIdx.x;
    const int lane = tid & 31;
    const int wid  = tid >> 5;                       // cols wid*32..+32
    const int bm   = blockIdx.x;
    const int gi   = tid >> 4;                       // scan group
    const int q    = tid & 15;                       // scan lane

    const int t0    = bm * NTILE;                    // first virtual tile
    const int row0  = t0 * 16;
    int nrows = BS - row0;
    nrows = nrows < 0 ? 0 : (nrows > MROWS ? MROWS : nrows);   // multiple of 16

    // ================= init: carry0 = te @ U_type + b_type =================
    {
        float* s_Ut = s_P;                           // [4][64][16] 16KB
        float* s_te = s_P + 4096;                    // [112][64]   28.7KB
        for (int j = tid; j < NAGG * TDIM * RANK / 4; j += 256)
            ((float4*)s_Ut)[j] = ((const float4*)Ut)[j];
        const float4* teg = (const float4*)(te + (size_t)row0 * TDIM);
        for (int j = tid; j < nrows * 16; j += 256)
            ((float4*)s_te)[j] = teg[j];
        __syncthreads();
        for (int idx = tid; idx < nrows * 64; idx += 256) {
            int b = idx >> 6, a = (idx >> 4) & 3, qq = idx & 15;
            float cr = bt[a * RANK + qq];
            const float* tep = s_te + b * TDIM;
            const float* utp = s_Ut + a * TDIM * RANK + qq;
            #pragma unroll
            for (int tt = 0; tt < TDIM; tt++)
                cr = fmaf(tep[tt], utp[tt * RANK], cr);
            s_carry[idx] = cr;
        }
        __syncthreads();
    }

    // ================= main loop over (c, a) =================
    for (int ca = 0; ca < NCA; ca++) {
        const int c = ca >> 2;
        const uint4* pAh = g_Afr_h + (((size_t)c * NBT_PAD + t0) * 16) * 32 + lane;
        const uint4* pAl = g_Afr_l + (((size_t)c * NBT_PAD + t0) * 16) * 32 + lane;
        const uint4* pB  = g_Bfr   + (((size_t)ca * 32 + wid * 4) * 16) * 32 + lane;

        // ---- prefetch kt=0 fragments + bias for this ca ----
        uint4 Ah[NTILE], Al[NTILE], Bq[4];
        #pragma unroll
        for (int mt = 0; mt < NTILE; mt++) {
            Ah[mt] = pAh[(size_t)(mt * 16) * 32];
            Al[mt] = pAl[(size_t)(mt * 16) * 32];
        }
        #pragma unroll
        for (int nf = 0; nf < 4; nf++)
            Bq[nf] = pB[(size_t)(nf * 16) * 32];
        float biasval = bb[(size_t)ca * RCOLS + tid];

        // ---- scan step for previous (c,a): overlaps the prefetch latency ----
        if (ca > 0) {
            const int pa = (ca - 1) & 3;
            float bq[RANK];
            #pragma unroll
            for (int r = 0; r < RANK; r++) bq[r] = s_bias[r * 16 + q];
            for (int b = gi; b < nrows; b += 16) {
                float cur = s_carry[b * 64 + pa * 16 + q];
                const float* Pb = s_P + (size_t)b * PPAD;
                float accv = 0.f;
                #pragma unroll
                for (int r = 0; r < RANK; r++) {
                    float m  = Pb[r * 16 + q] + bq[r];
                    float cr = __shfl_sync(0xffffffffu, cur, r, 16);
                    accv = fmaf(cr, m, accv);
                }
                float m15 = Pb[240 + q] + bq[15];
                s_carry[b * 64 + pa * 16 + q] = accv + m15;
            }
        }

        // ---- GEMM: M=112 N=256 K=256, bf16 3-pass, pass-OUTER ordering ----
        // (28 independent accumulators between reuses of the same one)
        float acc[NTILE][4][4];
        #pragma unroll
        for (int mt = 0; mt < NTILE; mt++)
            #pragma unroll
            for (int nf = 0; nf < 4; nf++)
                #pragma unroll
                for (int e = 0; e < 4; e++) acc[mt][nf][e] = 0.f;

        #pragma unroll 1
        for (int kt = 0; kt < 16; kt++) {
            // pass 0: Ah x Bh
            #pragma unroll
            for (int mt = 0; mt < NTILE; mt++)
                #pragma unroll
                for (int nf = 0; nf < 4; nf++)
                    mma16816(acc[mt][nf], Ah[mt].x, Ah[mt].y, Ah[mt].z, Ah[mt].w,
                             Bq[nf].x, Bq[nf].y);
            // pass 1: Al x Bh
            #pragma unroll
            for (int mt = 0; mt < NTILE; mt++)
                #pragma unroll
                for (int nf = 0; nf < 4; nf++)
                    mma16816(acc[mt][nf], Al[mt].x, Al[mt].y, Al[mt].z, Al[mt].w,
                             Bq[nf].x, Bq[nf].y);
            // pass 2: Ah x Bl
            #pragma unroll
            for (int mt = 0; mt < NTILE; mt++)
                #pragma unroll
                for (int nf = 0; nf < 4; nf++)
                    mma16816(acc[mt][nf], Ah[mt].x, Ah[mt].y, Ah[mt].z, Ah[mt].w,
                             Bq[nf].z, Bq[nf].w);
            if (kt < 15) {
                #pragma unroll
                for (int mt = 0; mt < NTILE; mt++) {
                    Ah[mt] = pAh[(size_t)(mt * 16 + kt + 1) * 32];
                    Al[mt] = pAl[(size_t)(mt * 16 + kt + 1) * 32];
                }
                #pragma unroll
                for (int nf = 0; nf < 4; nf++)
                    Bq[nf] = pB[(size_t)(nf * 16 + kt + 1) * 32];
            }
        }

        __syncthreads();   // all scans of (ca-1) done before s_P/s_bias rewrite
        s_bias[tid] = biasval;
        {
            int g = lane >> 2, tg = lane & 3;
            #pragma unroll
            for (int mt = 0; mt < NTILE; mt++) {
                int r_lo = mt * 16 + g;
                #pragma unroll
                for (int nf = 0; nf < 4; nf++) {
                    int col = wid * 32 + nf * 8 + tg * 2;
                    float2 lo = {acc[mt][nf][0], acc[mt][nf][1]};
                    float2 hi = {acc[mt][nf][2], acc[mt][nf][3]};
                    *(float2*)(s_P + (size_t)r_lo * PPAD + col)       = lo;
                    *(float2*)(s_P + (size_t)(r_lo + 8) * PPAD + col) = hi;
                }
            }
        }
        __syncthreads();
    }

    // ---- final scan step (ca = 31, a = 3) ----
    {
        float bq[RANK];
        #pragma unroll
        for (int r = 0; r < RANK; r++) bq[r] = s_bias[r * 16 + q];
        for (int b = gi; b < nrows; b += 16) {
            float cur = s_carry[b * 64 + 3 * 16 + q];
            const float* Pb = s_P + (size_t)b * PPAD;
            float accv = 0.f;
            #pragma unroll
            for (int r = 0; r < RANK; r++) {
                float m  = Pb[r * 16 + q] + bq[r];
                float cr = __shfl_sync(0xffffffffu, cur, r, 16);
                accv = fmaf(cr, m, accv);
            }
            float m15 = Pb[240 + q] + bq[15];
            s_carry[b * 64 + 3 * 16 + q] = accv + m15;
        }
    }

    // ================= output: out = carry @ U_output + b_output ============
    __syncthreads();
    float* s_Uo = s_P;                               // [4][16][256] 64KB
    for (int j = tid; j < NAGG * RANK * HDIM / 4; j += 256)
        ((float4*)s_Uo)[j] = ((const float4*)Uo)[j];
    __syncthreads();

    {
        const int hq = tid & 63;                     // h-group: h = hq*4
        const int bq4 = tid >> 6;                    // 0..3 sample offset
        for (int cb = 0; cb < NAGG; cb++) {
            float4 bov = ((const float4*)(bo + cb * HDIM))[hq];
            const float* uop = s_Uo + cb * RANK * HDIM;
            for (int b = bq4; b < nrows; b += 4) {
                const float* crp = s_carry + b * 64 + cb * 16;
                float4 o = bov;
                #pragma unroll
                for (int r = 0; r < RANK; r++) {
                    float cr = crp[r];
                    float4 u = ((const float4*)(uop + r * HDIM))[hq];
                    o.x = fmaf(cr, u.x, o.x);
                    o.y = fmaf(cr, u.y, o.y);
                    o.z = fmaf(cr, u.z, o.z);
                    o.w = fmaf(cr, u.w, o.w);
                }
                ((float4*)(out + ((size_t)row0 + b) * (NAGG * HDIM) + cb * HDIM))[hq] = o;
            }
        }
    }
}

// ---------------------------------------------------------------------------
extern "C" void kernel_launch(void* const* d_in, const int* in_sizes, int n_in,
                              void* d_out, int out_size) {
    const float* nb = (const float*)d_in[0];
    const float* te = (const float*)d_in[1];
    const float* U  = (const float*)d_in[2];
    const float* bb = (const float*)d_in[3];
    const float* Ut = (const float*)d_in[4];
    const float* bt = (const float*)d_in[5];
    const float* Uo = (const float*)d_in[6];
    const float* bo = (const float*)d_in[7];
    float* out = (float*)d_out;

    cudaFuncSetAttribute(tt_fused, cudaFuncAttributeMaxDynamicSharedMemorySize,
                         SMEM_TOT);

    tt_prep_a<<<(int)((size_t)NCH * NBT * 16 * 32 / 256), 256>>>(nb);
    tt_prep_b<<<(int)((size_t)NCA * 32 * 16 * 32 / 256), 256>>>(U);
    tt_fused<<<NCTA, 256, SMEM_TOT>>>(te, bb, Ut, bt, Uo, bo, out);
}

// round 9
// speedup vs baseline: 1.0672x; 1.0672x over previous
#include <cuda_runtime.h>
#include <cuda_bf16.h>
#include <cstdint>

#define BS    16384
#define NCH   8
#define HDIM  256
#define RANK  16
#define NAGG  4
#define TDIM  64
#define RCOLS 272
#define NEED  256
#define NCA   (NCH*NAGG)        // 32
#define NBT   (BS/16)           // 1024 16-row tiles (exact, no padding)
#define NTILE 4                 // tiles per CTA
#define NCTA  (NBT/NTILE)       // 256 CTAs, 2 resident per SM
#define MROWS (NTILE*16)        // 64 rows per CTA

// ---------------- fragment-major operand scratch ---------------------------
// A frags: [c][tile(1024)][kt(16)][lane(32)] x uint4 ; hi and lo
__device__ uint4 g_Afr_h[(size_t)NCH * NBT * 16 * 32];
__device__ uint4 g_Afr_l[(size_t)NCH * NBT * 16 * 32];
// B frags packed: [ca][nt(32)][kt(16)][lane(32)] x uint4 {bh0,bh1,bl0,bl1}
__device__ uint4 g_Bfr[(size_t)NCA * 32 * 16 * 32];

// ---------------- helpers ---------------------------------------------------
__device__ __forceinline__ uint32_t pack_hi2(float x, float y) {
    __nv_bfloat162 p = {__float2bfloat16(x), __float2bfloat16(y)};
    return *(uint32_t*)&p;
}
__device__ __forceinline__ uint32_t pack_lo2(float x, float y) {
    float hx = __bfloat162float(__float2bfloat16(x));
    float hy = __bfloat162float(__float2bfloat16(y));
    __nv_bfloat162 p = {__float2bfloat16(x - hx), __float2bfloat16(y - hy)};
    return *(uint32_t*)&p;
}
// volatile: R6-proven codegen (627us) — keeps ptxas from inflating live ranges
__device__ __forceinline__ void mma16816(float* d, uint32_t a0, uint32_t a1,
                                         uint32_t a2, uint32_t a3,
                                         uint32_t b0, uint32_t b1) {
    asm volatile(
        "mma.sync.aligned.m16n8k16.row.col.f32.bf16.bf16.f32 "
        "{%0,%1,%2,%3}, {%4,%5,%6,%7}, {%8,%9}, {%0,%1,%2,%3};"
        : "+f"(d[0]), "+f"(d[1]), "+f"(d[2]), "+f"(d[3])
        : "r"(a0), "r"(a1), "r"(a2), "r"(a3), "r"(b0), "r"(b1));
}

// ---------------- prep A: nb fp32 -> hi/lo bf16 mma fragments ---------------
__global__ __launch_bounds__(256) void tt_prep_a(const float* __restrict__ nb) {
    size_t t = (size_t)blockIdx.x * 256 + threadIdx.x;   // [c][bt(1024)][kt][lane]
    int lane = (int)(t & 31);
    int kt   = (int)((t >> 5) & 15);
    int bt   = (int)((t >> 9) & (NBT - 1));
    int c    = (int)(t >> 19);
    int g = lane >> 2, tg = lane & 3;
    int r0 = bt * 16 + g, r1 = r0 + 8;
    int k0 = kt * 16 + tg * 2;
    const float* p0 = nb + ((size_t)r0 * NCH + c) * HDIM;
    const float* p1 = nb + ((size_t)r1 * NCH + c) * HDIM;
    float2 v0 = *(const float2*)(p0 + k0);
    float2 v1 = *(const float2*)(p1 + k0);
    float2 v2 = *(const float2*)(p0 + k0 + 8);
    float2 v3 = *(const float2*)(p1 + k0 + 8);
    size_t o = (((size_t)c * NBT + bt) * 16 + kt) * 32 + lane;
    g_Afr_h[o] = make_uint4(pack_hi2(v0.x, v0.y), pack_hi2(v1.x, v1.y),
                            pack_hi2(v2.x, v2.y), pack_hi2(v3.x, v3.y));
    g_Afr_l[o] = make_uint4(pack_lo2(v0.x, v0.y), pack_lo2(v1.x, v1.y),
                            pack_lo2(v2.x, v2.y), pack_lo2(v3.x, v3.y));
}

// ---------------- prep B: U fp32 -> packed hi/lo bf16 fragments -------------
__global__ __launch_bounds__(256) void tt_prep_b(const float* __restrict__ U) {
    size_t t = (size_t)blockIdx.x * 256 + threadIdx.x;   // [ca][nt(32)][kt][lane]
    int lane = (int)(t & 31);
    int kt   = (int)((t >> 5) & 15);
    int nt   = (int)((t >> 9) & 31);
    int ca   = (int)(t >> 14);
    int g = lane >> 2, tg = lane & 3;
    int n  = nt * 8 + g;
    int k0 = kt * 16 + tg * 2;
    const float* base = U + (size_t)ca * HDIM * RCOLS + n;
    float x0 = base[(size_t)(k0)     * RCOLS];
    float x1 = base[(size_t)(k0 + 1) * RCOLS];
    float x2 = base[(size_t)(k0 + 8) * RCOLS];
    float x3 = base[(size_t)(k0 + 9) * RCOLS];
    g_Bfr[t] = make_uint4(pack_hi2(x0, x1), pack_hi2(x2, x3),
                          pack_lo2(x0, x1), pack_lo2(x2, x3));
}

// ---------------- fused kernel ----------------------------------------------
#define PPAD      264
#define OFF_BIAS  (MROWS * 64 * 4)            // carry: 64*64*4 = 16384
#define OFF_P     (OFF_BIAS + 1024)           // 17408
#define SMEM_TOT  (OFF_P + MROWS * PPAD * 4)  // 84992  (2 CTAs/SM fit)

__global__ __launch_bounds__(256, 2) void tt_fused(
    const float* __restrict__ te,   // [BS][TDIM]
    const float* __restrict__ bb,   // [NCH][NAGG][1][RCOLS]
    const float* __restrict__ Ut,   // [NAGG][TDIM][RANK]
    const float* __restrict__ bt,   // [NAGG][1][RANK]
    const float* __restrict__ Uo,   // [NAGG][RANK][HDIM]
    const float* __restrict__ bo,   // [NAGG][1][HDIM]
    float* __restrict__ out)        // [BS][NAGG*HDIM]
{
    extern __shared__ char smem[];
    float* s_carry = (float*)smem;                   // [64][4][16]
    float* s_bias  = (float*)(smem + OFF_BIAS);      // [256]
    float* s_P     = (float*)(smem + OFF_P);         // [64][264]

    const int tid  = threadIdx.x;
    const int lane = tid & 31;
    const int wid  = tid >> 5;
    const int mg   = wid >> 2;                       // m-group: tiles mg*2, mg*2+1
    const int ng   = wid & 3;                        // n-group: cols ng*64..+63
    const int bm   = blockIdx.x;
    const int gi   = tid >> 4;                       // scan group
    const int q    = tid & 15;                       // scan lane

    const int t0   = bm * NTILE;
    const int row0 = t0 * 16;

    // ================= init: carry0 = te @ U_type + b_type =================
    {
        float* s_Ut = s_P;                           // [4][64][16] 16KB
        float* s_te = s_P + 4096;                    // [64][64]    16KB
        for (int j = tid; j < NAGG * TDIM * RANK / 4; j += 256)
            ((float4*)s_Ut)[j] = ((const float4*)Ut)[j];
        const float4* teg = (const float4*)(te + (size_t)row0 * TDIM);
        for (int j = tid; j < MROWS * 16; j += 256)
            ((float4*)s_te)[j] = teg[j];
        __syncthreads();
        for (int idx = tid; idx < MROWS * 64; idx += 256) {
            int b = idx >> 6, a = (idx >> 4) & 3, qq = idx & 15;
            float cr = bt[a * RANK + qq];
            const float* tep = s_te + b * TDIM;
            const float* utp = s_Ut + a * TDIM * RANK + qq;
            #pragma unroll
            for (int tt = 0; tt < TDIM; tt++)
                cr = fmaf(tep[tt], utp[tt * RANK], cr);
            s_carry[idx] = cr;
        }
        __syncthreads();
    }

    // ================= main loop over (c, a) =================
    for (int ca = 0; ca < NCA; ca++) {
        const int c = ca >> 2;
        const uint4* pA0 = g_Afr_h + (((size_t)c * NBT + t0 + mg * 2) * 16) * 32 + lane;
        const uint4* pA1 = g_Afr_l + (((size_t)c * NBT + t0 + mg * 2) * 16) * 32 + lane;
        const uint4* pB  = g_Bfr   + (((size_t)ca * 32 + ng * 8) * 16) * 32 + lane;

        float biasval = bb[(size_t)ca * RCOLS + tid];

        // ---- scan step for previous (c,a): overlaps operand warm-up --------
        if (ca > 0) {
            const int pa = (ca - 1) & 3;
            float bq[RANK];
            #pragma unroll
            for (int r = 0; r < RANK; r++) bq[r] = s_bias[r * 16 + q];
            #pragma unroll
            for (int b = gi; b < MROWS; b += 16) {
                float cur = s_carry[b * 64 + pa * 16 + q];
                const float* Pb = s_P + (size_t)b * PPAD;
                float accv = 0.f;
                #pragma unroll
                for (int r = 0; r < RANK; r++) {
                    float m  = Pb[r * 16 + q] + bq[r];
                    float cr = __shfl_sync(0xffffffffu, cur, r, 16);
                    accv = fmaf(cr, m, accv);
                }
                float m15 = Pb[240 + q] + bq[15];
                s_carry[b * 64 + pa * 16 + q] = accv + m15;
            }
        }

        // ---- GEMM: per warp 32 rows x 64 cols, K=256, bf16 3-pass ----
        float acc[2][8][4];
        #pragma unroll
        for (int mt = 0; mt < 2; mt++)
            #pragma unroll
            for (int nf = 0; nf < 8; nf++)
                #pragma unroll
                for (int e = 0; e < 4; e++) acc[mt][nf][e] = 0.f;

        #pragma unroll 1
        for (int kt = 0; kt < 16; kt++) {
            uint4 Ah0 = pA0[(size_t)(0 * 16 + kt) * 32];
            uint4 Ah1 = pA0[(size_t)(1 * 16 + kt) * 32];
            uint4 Al0 = pA1[(size_t)(0 * 16 + kt) * 32];
            uint4 Al1 = pA1[(size_t)(1 * 16 + kt) * 32];
            #pragma unroll
            for (int nf = 0; nf < 8; nf++) {
                uint4 Bq = pB[(size_t)(nf * 16 + kt) * 32];
                mma16816(acc[0][nf], Ah0.x, Ah0.y, Ah0.z, Ah0.w, Bq.x, Bq.y);
                mma16816(acc[1][nf], Ah1.x, Ah1.y, Ah1.z, Ah1.w, Bq.x, Bq.y);
                mma16816(acc[0][nf], Al0.x, Al0.y, Al0.z, Al0.w, Bq.x, Bq.y);
                mma16816(acc[1][nf], Al1.x, Al1.y, Al1.z, Al1.w, Bq.x, Bq.y);
                mma16816(acc[0][nf], Ah0.x, Ah0.y, Ah0.z, Ah0.w, Bq.z, Bq.w);
                mma16816(acc[1][nf], Ah1.x, Ah1.y, Ah1.z, Ah1.w, Bq.z, Bq.w);
            }
        }

        __syncthreads();   // scans of (ca-1) done before s_P/s_bias rewrite
        s_bias[tid] = biasval;
        {
            int g = lane >> 2, tg = lane & 3;
            #pragma unroll
            for (int mt = 0; mt < 2; mt++) {
                int r_lo = (mg * 2 + mt) * 16 + g;
                #pragma unroll
                for (int nf = 0; nf < 8; nf++) {
                    int col = ng * 64 + nf * 8 + tg * 2;
                    float2 lo = {acc[mt][nf][0], acc[mt][nf][1]};
                    float2 hi = {acc[mt][nf][2], acc[mt][nf][3]};
                    *(float2*)(s_P + (size_t)r_lo * PPAD + col)       = lo;
                    *(float2*)(s_P + (size_t)(r_lo + 8) * PPAD + col) = hi;
                }
            }
        }
        __syncthreads();
    }

    // ---- final scan step (ca = 31, a = 3) ----
    {
        float bq[RANK];
        #pragma unroll
        for (int r = 0; r < RANK; r++) bq[r] = s_bias[r * 16 + q];
        #pragma unroll
        for (int b = gi; b < MROWS; b += 16) {
            float cur = s_carry[b * 64 + 3 * 16 + q];
            const float* Pb = s_P + (size_t)b * PPAD;
            float accv = 0.f;
            #pragma unroll
            for (int r = 0; r < RANK; r++) {
                float m  = Pb[r * 16 + q] + bq[r];
                float cr = __shfl_sync(0xffffffffu, cur, r, 16);
                accv = fmaf(cr, m, accv);
            }
            float m15 = Pb[240 + q] + bq[15];
            s_carry[b * 64 + 3 * 16 + q] = accv + m15;
        }
    }

    // ================= output: out = carry @ U_output + b_output ============
    __syncthreads();
    float* s_Uo = s_P;                               // [4][16][256] 64KB
    for (int j = tid; j < NAGG * RANK * HDIM / 4; j += 256)
        ((float4*)s_Uo)[j] = ((const float4*)Uo)[j];
    __syncthreads();

    {
        const int hq = tid & 63;                     // h = hq*4
        const int bq4 = tid >> 6;                    // 0..3 sample offset
        for (int cb = 0; cb < NAGG; cb++) {
            float4 bov = ((const float4*)(bo + cb * HDIM))[hq];
            const float* uop = s_Uo + cb * RANK * HDIM;
            #pragma unroll
            for (int b = bq4; b < MROWS; b += 4) {
                const float* crp = s_carry + b * 64 + cb * 16;
                float4 o = bov;
                #pragma unroll
                for (int r = 0; r < RANK; r++) {
                    float cr = crp[r];
                    float4 u = ((const float4*)(uop + r * HDIM))[hq];
                    o.x = fmaf(cr, u.x, o.x);
                    o.y = fmaf(cr, u.y, o.y);
                    o.z = fmaf(cr, u.z, o.z);
                    o.w = fmaf(cr, u.w, o.w);
                }
                ((float4*)(out + ((size_t)row0 + b) * (NAGG * HDIM) + cb * HDIM))[hq] = o;
            }
        }
    }
}

// ---------------------------------------------------------------------------
extern "C" void kernel_launch(void* const* d_in, const int* in_sizes, int n_in,
                              void* d_out, int out_size) {
    const float* nb = (const float*)d_in[0];
    const float* te = (const float*)d_in[1];
    const float* U  = (const float*)d_in[2];
    const float* bb = (const float*)d_in[3];
    const float* Ut = (const float*)d_in[4];
    const float* bt = (const float*)d_in[5];
    const float* Uo = (const float*)d_in[6];
    const float* bo = (const float*)d_in[7];
    float* out = (float*)d_out;

    cudaFuncSetAttribute(tt_fused, cudaFuncAttributeMaxDynamicSharedMemorySize,
                         SMEM_TOT);

    tt_prep_a<<<(int)((size_t)NCH * NBT * 16 * 32 / 256), 256>>>(nb);
    tt_prep_b<<<(int)((size_t)NCA * 32 * 16 * 32 / 256), 256>>>(U);
    tt_fused<<<NCTA, 256, SMEM_TOT>>>(te, bb, Ut, bt, Uo, bo, out);
}

// round 10
// speedup vs baseline: 1.1839x; 1.1094x over previous
#include <cuda_runtime.h>
#include <cuda_bf16.h>
#include <cstdint>

#define BS    16384
#define NCH   8
#define HDIM  256
#define RANK  16
#define NAGG  4
#define TDIM  64
#define RCOLS 272
#define NEED  256
#define NCA   (NCH*NAGG)        // 32
#define NBT   (BS/16)           // 1024 real 16-row tiles
#define NTILE 7                 // tiles per CTA (uniform)
#define NCTA  148
#define NBT_PAD (NCTA*NTILE)    // 1036 virtual tiles
#define MROWS (NTILE*16)        // 112 rows per CTA

// ---------------- fragment-major operand scratch ---------------------------
// A frags: [c][tile(1036)][kt(16)][lane(32)] x uint4 ; hi and lo
__device__ uint4 g_Afr_h[(size_t)NCH * NBT_PAD * 16 * 32];
__device__ uint4 g_Afr_l[(size_t)NCH * NBT_PAD * 16 * 32];
// B frags packed: [ca][nt(32)][kt(16)][lane(32)] x uint4 {bh0,bh1,bl0,bl1}
__device__ uint4 g_Bfr[(size_t)NCA * 32 * 16 * 32];

// ---------------- helpers ---------------------------------------------------
__device__ __forceinline__ uint32_t pack_hi2(float x, float y) {
    __nv_bfloat162 p = {__float2bfloat16(x), __float2bfloat16(y)};
    return *(uint32_t*)&p;
}
__device__ __forceinline__ uint32_t pack_lo2(float x, float y) {
    float hx = __bfloat162float(__float2bfloat16(x));
    float hy = __bfloat162float(__float2bfloat16(y));
    __nv_bfloat162 p = {__float2bfloat16(x - hx), __float2bfloat16(y - hy)};
    return *(uint32_t*)&p;
}
// volatile: exact emission order preserved (R6-proven codegen discipline)
__device__ __forceinline__ void mma16816(float* d, uint32_t a0, uint32_t a1,
                                         uint32_t a2, uint32_t a3,
                                         uint32_t b0, uint32_t b1) {
    asm volatile(
        "mma.sync.aligned.m16n8k16.row.col.f32.bf16.bf16.f32 "
        "{%0,%1,%2,%3}, {%4,%5,%6,%7}, {%8,%9}, {%0,%1,%2,%3};"
        : "+f"(d[0]), "+f"(d[1]), "+f"(d[2]), "+f"(d[3])
        : "r"(a0), "r"(a1), "r"(a2), "r"(a3), "r"(b0), "r"(b1));
}

// ---------------- prep A: nb fp32 -> hi/lo bf16 mma fragments ---------------
__global__ __launch_bounds__(256) void tt_prep_a(const float* __restrict__ nb) {
    size_t t = (size_t)blockIdx.x * 256 + threadIdx.x;   // [c][bt(1024)][kt][lane]
    int lane = (int)(t & 31);
    int kt   = (int)((t >> 5) & 15);
    int bt   = (int)((t >> 9) & (NBT - 1));
    int c    = (int)(t >> 19);
    int g = lane >> 2, tg = lane & 3;
    int r0 = bt * 16 + g, r1 = r0 + 8;
    int k0 = kt * 16 + tg * 2;
    const float* p0 = nb + ((size_t)r0 * NCH + c) * HDIM;
    const float* p1 = nb + ((size_t)r1 * NCH + c) * HDIM;
    float2 v0 = *(const float2*)(p0 + k0);
    float2 v1 = *(const float2*)(p1 + k0);
    float2 v2 = *(const float2*)(p0 + k0 + 8);
    float2 v3 = *(const float2*)(p1 + k0 + 8);
    size_t o = (((size_t)c * NBT_PAD + bt) * 16 + kt) * 32 + lane;
    g_Afr_h[o] = make_uint4(pack_hi2(v0.x, v0.y), pack_hi2(v1.x, v1.y),
                            pack_hi2(v2.x, v2.y), pack_hi2(v3.x, v3.y));
    g_Afr_l[o] = make_uint4(pack_lo2(v0.x, v0.y), pack_lo2(v1.x, v1.y),
                            pack_lo2(v2.x, v2.y), pack_lo2(v3.x, v3.y));
}

// ---------------- prep B: U fp32 -> packed hi/lo bf16 fragments -------------
__global__ __launch_bounds__(256) void tt_prep_b(const float* __restrict__ U) {
    size_t t = (size_t)blockIdx.x * 256 + threadIdx.x;   // [ca][nt(32)][kt][lane]
    int lane = (int)(t & 31);
    int kt   = (int)((t >> 5) & 15);
    int nt   = (int)((t >> 9) & 31);
    int ca   = (int)(t >> 14);
    int g = lane >> 2, tg = lane & 3;
    int n  = nt * 8 + g;
    int k0 = kt * 16 + tg * 2;
    const float* base = U + (size_t)ca * HDIM * RCOLS + n;
    float x0 = base[(size_t)(k0)     * RCOLS];
    float x1 = base[(size_t)(k0 + 1) * RCOLS];
    float x2 = base[(size_t)(k0 + 8) * RCOLS];
    float x3 = base[(size_t)(k0 + 9) * RCOLS];
    g_Bfr[t] = make_uint4(pack_hi2(x0, x1), pack_hi2(x2, x3),
                          pack_lo2(x0, x1), pack_lo2(x2, x3));
}

// ---------------- fused kernel ----------------------------------------------
#define PPAD      264
#define OFF_BIAS  (MROWS * 64 * 4)            // carry: 112*64*4 = 28672
#define OFF_P     (OFF_BIAS + 1024)           // 29696
#define SMEM_TOT  (OFF_P + MROWS * PPAD * 4)  // 147968

__global__ __launch_bounds__(256, 1) void tt_fused(
    const float* __restrict__ te,   // [BS][TDIM]
    const float* __restrict__ bb,   // [NCH][NAGG][1][RCOLS]
    const float* __restrict__ Ut,   // [NAGG][TDIM][RANK]
    const float* __restrict__ bt,   // [NAGG][1][RANK]
    const float* __restrict__ Uo,   // [NAGG][RANK][HDIM]
    const float* __restrict__ bo,   // [NAGG][1][HDIM]
    float* __restrict__ out)        // [BS][NAGG*HDIM]
{
    extern __shared__ char smem[];
    float* s_carry = (float*)smem;                   // [112][4][16]
    float* s_bias  = (float*)(smem + OFF_BIAS);      // [256]
    float* s_P     = (float*)(smem + OFF_P);         // [112][264]

    const int tid  = threadIdx.x;
    const int lane = tid & 31;
    const int wid  = tid >> 5;                       // cols wid*32..+32
    const int bm   = blockIdx.x;
    const int gi   = tid >> 4;                       // scan group
    const int q    = tid & 15;                       // scan lane

    const int t0    = bm * NTILE;                    // first virtual tile
    const int row0  = t0 * 16;
    int nrows = BS - row0;
    nrows = nrows < 0 ? 0 : (nrows > MROWS ? MROWS : nrows);   // multiple of 16

    // ================= init: carry0 = te @ U_type + b_type =================
    {
        float* s_Ut = s_P;                           // [4][64][16] 16KB
        float* s_te = s_P + 4096;                    // [112][64]   28.7KB
        for (int j = tid; j < NAGG * TDIM * RANK / 4; j += 256)
            ((float4*)s_Ut)[j] = ((const float4*)Ut)[j];
        const float4* teg = (const float4*)(te + (size_t)row0 * TDIM);
        for (int j = tid; j < nrows * 16; j += 256)
            ((float4*)s_te)[j] = teg[j];
        __syncthreads();
        for (int idx = tid; idx < nrows * 64; idx += 256) {
            int b = idx >> 6, a = (idx >> 4) & 3, qq = idx & 15;
            float cr = bt[a * RANK + qq];
            const float* tep = s_te + b * TDIM;
            const float* utp = s_Ut + a * TDIM * RANK + qq;
            #pragma unroll
            for (int tt = 0; tt < TDIM; tt++)
                cr = fmaf(tep[tt], utp[tt * RANK], cr);
            s_carry[idx] = cr;
        }
        __syncthreads();
    }

    // ================= main loop over (c, a) =================
    for (int ca = 0; ca < NCA; ca++) {
        const int c = ca >> 2;
        const uint4* pAh = g_Afr_h + (((size_t)c * NBT_PAD + t0) * 16) * 32 + lane;
        const uint4* pAl = g_Afr_l + (((size_t)c * NBT_PAD + t0) * 16) * 32 + lane;
        const uint4* pB  = g_Bfr   + (((size_t)ca * 32 + wid * 4) * 16) * 32 + lane;

        // ---- prefetch kt=0 fragments + bias for this ca ----
        uint4 Ah[NTILE], Al[NTILE], Bq[4];
        #pragma unroll
        for (int mt = 0; mt < NTILE; mt++) {
            Ah[mt] = pAh[(size_t)(mt * 16) * 32];
            Al[mt] = pAl[(size_t)(mt * 16) * 32];
        }
        #pragma unroll
        for (int nf = 0; nf < 4; nf++)
            Bq[nf] = pB[(size_t)(nf * 16) * 32];
        float biasval = bb[(size_t)ca * RCOLS + tid];

        // ---- scan step for previous (c,a): overlaps the prefetch latency ----
        if (ca > 0) {
            const int pa = (ca - 1) & 3;
            float bq[RANK];
            #pragma unroll
            for (int r = 0; r < RANK; r++) bq[r] = s_bias[r * 16 + q];
            for (int b = gi; b < nrows; b += 16) {
                float cur = s_carry[b * 64 + pa * 16 + q];
                const float* Pb = s_P + (size_t)b * PPAD;
                float accv = 0.f;
                #pragma unroll
                for (int r = 0; r < RANK; r++) {
                    float m  = Pb[r * 16 + q] + bq[r];
                    float cr = __shfl_sync(0xffffffffu, cur, r, 16);
                    accv = fmaf(cr, m, accv);
                }
                float m15 = Pb[240 + q] + bq[15];
                s_carry[b * 64 + pa * 16 + q] = accv + m15;
            }
        }

        // ---- GEMM: M=112 N=256 K=256, bf16 3-pass ----
        // Pass-sweep emission: RAW distance per accumulator = 28 MMAs
        // (same per-acc accumulation order as R6 -> identical numerics).
        float acc[NTILE][4][4];
        #pragma unroll
        for (int mt = 0; mt < NTILE; mt++)
            #pragma unroll
            for (int nf = 0; nf < 4; nf++)
                #pragma unroll
                for (int e = 0; e < 4; e++) acc[mt][nf][e] = 0.f;

        #pragma unroll 1
        for (int kt = 0; kt < 16; kt++) {
            // sweep 0: Ah x Bh (28 independent MMAs)
            #pragma unroll
            for (int mt = 0; mt < NTILE; mt++)
                #pragma unroll
                for (int nf = 0; nf < 4; nf++)
                    mma16816(acc[mt][nf], Ah[mt].x, Ah[mt].y, Ah[mt].z, Ah[mt].w,
                             Bq[nf].x, Bq[nf].y);
            // sweep 1: Al x Bh (last use of Al)
            #pragma unroll
            for (int mt = 0; mt < NTILE; mt++)
                #pragma unroll
                for (int nf = 0; nf < 4; nf++)
                    mma16816(acc[mt][nf], Al[mt].x, Al[mt].y, Al[mt].z, Al[mt].w,
                             Bq[nf].x, Bq[nf].y);
            // Al prefetch for kt+1 (Al free now; overlaps sweep 2 issue)
            if (kt < 15) {
                #pragma unroll
                for (int mt = 0; mt < NTILE; mt++)
                    Al[mt] = pAl[(size_t)(mt * 16 + kt + 1) * 32];
            }
            // sweep 2: Ah x Bl
            #pragma unroll
            for (int mt = 0; mt < NTILE; mt++)
                #pragma unroll
                for (int nf = 0; nf < 4; nf++)
                    mma16816(acc[mt][nf], Ah[mt].x, Ah[mt].y, Ah[mt].z, Ah[mt].w,
                             Bq[nf].z, Bq[nf].w);
            // Ah + B prefetch for kt+1
            if (kt < 15) {
                #pragma unroll
                for (int mt = 0; mt < NTILE; mt++)
                    Ah[mt] = pAh[(size_t)(mt * 16 + kt + 1) * 32];
                #pragma unroll
                for (int nf = 0; nf < 4; nf++)
                    Bq[nf] = pB[(size_t)(nf * 16 + kt + 1) * 32];
            }
        }

        __syncthreads();   // all scans of (ca-1) done before s_P/s_bias rewrite
        s_bias[tid] = biasval;
        {
            int g = lane >> 2, tg = lane & 3;
            #pragma unroll
            for (int mt = 0; mt < NTILE; mt++) {
                int r_lo = mt * 16 + g;
                #pragma unroll
                for (int nf = 0; nf < 4; nf++) {
                    int col = wid * 32 + nf * 8 + tg * 2;
                    float2 lo = {acc[mt][nf][0], acc[mt][nf][1]};
                    float2 hi = {acc[mt][nf][2], acc[mt][nf][3]};
                    *(float2*)(s_P + (size_t)r_lo * PPAD + col)       = lo;
                    *(float2*)(s_P + (size_t)(r_lo + 8) * PPAD + col) = hi;
                }
            }
        }
        __syncthreads();
    }

    // ---- final scan step (ca = 31, a = 3) ----
    {
        float bq[RANK];
        #pragma unroll
        for (int r = 0; r < RANK; r++) bq[r] = s_bias[r * 16 + q];
        for (int b = gi; b < nrows; b += 16) {
            float cur = s_carry[b * 64 + 3 * 16 + q];
            const float* Pb = s_P + (size_t)b * PPAD;
            float accv = 0.f;
            #pragma unroll
            for (int r = 0; r < RANK; r++) {
                float m  = Pb[r * 16 + q] + bq[r];
                float cr = __shfl_sync(0xffffffffu, cur, r, 16);
                accv = fmaf(cr, m, accv);
            }
            float m15 = Pb[240 + q] + bq[15];
            s_carry[b * 64 + 3 * 16 + q] = accv + m15;
        }
    }

    // ================= output: out = carry @ U_output + b_output ============
    __syncthreads();
    float* s_Uo = s_P;                               // [4][16][256] 64KB
    for (int j = tid; j < NAGG * RANK * HDIM / 4; j += 256)
        ((float4*)s_Uo)[j] = ((const float4*)Uo)[j];
    __syncthreads();

    {
        const int hq = tid & 63;                     // h-group: h = hq*4
        const int bq4 = tid >> 6;                    // 0..3 sample offset
        for (int cb = 0; cb < NAGG; cb++) {
            float4 bov = ((const float4*)(bo + cb * HDIM))[hq];
            const float* uop = s_Uo + cb * RANK * HDIM;
            for (int b = bq4; b < nrows; b += 4) {
                const float* crp = s_carry + b * 64 + cb * 16;
                float4 o = bov;
                #pragma unroll
                for (int r = 0; r < RANK; r++) {
                    float cr = crp[r];
                    float4 u = ((const float4*)(uop + r * HDIM))[hq];
                    o.x = fmaf(cr, u.x, o.x);
                    o.y = fmaf(cr, u.y, o.y);
                    o.z = fmaf(cr, u.z, o.z);
                    o.w = fmaf(cr, u.w, o.w);
                }
                ((float4*)(out + ((size_t)row0 + b) * (NAGG * HDIM) + cb * HDIM))[hq] = o;
            }
        }
    }
}

// ---------------------------------------------------------------------------
extern "C" void kernel_launch(void* const* d_in, const int* in_sizes, int n_in,
                              void* d_out, int out_size) {
    const float* nb = (const float*)d_in[0];
    const float* te = (const float*)d_in[1];
    const float* U  = (const float*)d_in[2];
    const float* bb = (const float*)d_in[3];
    const float* Ut = (const float*)d_in[4];
    const float* bt = (const float*)d_in[5];
    const float* Uo = (const float*)d_in[6];
    const float* bo = (const float*)d_in[7];
    float* out = (float*)d_out;

    cudaFuncSetAttribute(tt_fused, cudaFuncAttributeMaxDynamicSharedMemorySize,
                         SMEM_TOT);

    tt_prep_a<<<(int)((size_t)NCH * NBT * 16 * 32 / 256), 256>>>(nb);
    tt_prep_b<<<(int)((size_t)NCA * 32 * 16 * 32 / 256), 256>>>(U);
    tt_fused<<<NCTA, 256, SMEM_TOT>>>(te, bb, Ut, bt, Uo, bo, out);
}